// round 16
// baseline (speedup 1.0000x reference)
#include <cuda_runtime.h>
#include <cuda_bf16.h>

#define EMSG  131072
#define NNODE 8192
#define DDIM  256
#define NB    512
#define PCAP  64
#define TM    128
#define SST   8
#define NTILE (NNODE/TM)
#define PB    264
#define PAr   20

// k_mma dynamic smem (bytes)
#define OFF_AH 0
#define OFF_AL 20480
#define OFF_BH 40960
#define OFF_BL 74752
#define SMEM_SZ 108544

typedef unsigned long long u64;

__device__ int   g_counts [NNODE];
__device__ int   g_offsets[NNODE];
__device__ int   g_cursor [NNODE];
__device__ int   g_ids    [EMSG];
__device__ float g_tk     [EMSG];
__device__ int   g_order  [NNODE];
__device__ int   g_kbins  [NB];
__device__ int   g_koff   [NB];
__device__ int   g_kcur   [NB];
__device__ int   g_pmax;
__device__ int   g_gidx   [PCAP * NNODE];
__device__ int   g_nodeOf [NNODE];
__device__ int   g_Kof    [NNODE];
__device__ __align__(16) float    g_Wp [PCAP][DDIM*DDIM];   // (W^p)^T fp32
__device__ __align__(16) unsigned g_WH [PCAP][128*DDIM];    // W bf16x2 hi (k-pair packed)
__device__ __align__(16) unsigned g_WL [PCAP][128*DDIM];    // W bf16x2 lo
__device__ __align__(16) unsigned g_MH [EMSG][128];         // msg bf16x2 hi [id][kpair]
__device__ __align__(16) unsigned g_ML [EMSG][128];         // msg bf16x2 lo
__device__ __align__(16) float    g_v  [PCAP][DDIM];
__device__ __align__(16) float    g_cb [PCAP+1][DDIM];
__device__ __align__(16) float    g_part[SST * NNODE * DDIM];

__device__ __forceinline__ void split2(float x0, float x1, unsigned& hi, unsigned& lo) {
    __nv_bfloat16 h0 = __float2bfloat16(x0);
    __nv_bfloat16 h1 = __float2bfloat16(x1);
    float r0 = x0 - __bfloat162float(h0);
    float r1 = x1 - __bfloat162float(h1);
    __nv_bfloat162 H; H.x = h0; H.y = h1;
    __nv_bfloat162 L = __floats2bfloat162_rn(r0, r1);
    hi = *(unsigned*)&H; lo = *(unsigned*)&L;
}

#define MMA_BF16(c, A0, A1, A2, A3, B0, B1) \
    asm volatile("mma.sync.aligned.m16n8k16.row.col.f32.bf16.bf16.f32 " \
        "{%0,%1,%2,%3}, {%4,%5,%6,%7}, {%8,%9}, {%0,%1,%2,%3};" \
        : "+f"(c[0]), "+f"(c[1]), "+f"(c[2]), "+f"(c[3]) \
        : "r"(A0), "r"(A1), "r"(A2), "r"(A3), "r"(B0), "r"(B1))

static __device__ __forceinline__ unsigned smem_u32(const void* p) {
    unsigned a;
    asm("{ .reg .u64 t; cvta.to.shared.u64 t, %1; cvt.u32.u64 %0, t; }" : "=r"(a) : "l"(p));
    return a;
}

// ---------------- setup ----------------
__global__ void k_init() {
    int i = blockIdx.x * blockDim.x + threadIdx.x;
    if (i < NNODE) { g_counts[i] = 0; g_cursor[i] = 0; }
    if (i < NB)    { g_kbins[i]  = 0; g_kcur[i]   = 0; }
    if (i == 0)    g_pmax = 0;
}
__global__ void k_hist(const int* __restrict__ idx) {
    int e = blockIdx.x * blockDim.x + threadIdx.x;
    if (e < EMSG) atomicAdd(&g_counts[idx[e]], 1);
}
__global__ void k_pmax() {
    __shared__ int sm_;
    if (threadIdx.x == 0) sm_ = 0;
    __syncthreads();
    int n = blockIdx.x * blockDim.x + threadIdx.x;
    int v = (n < NNODE) ? min(g_counts[n], PCAP) : 0;
#pragma unroll
    for (int o = 16; o > 0; o >>= 1) v = max(v, __shfl_down_sync(~0u, v, o));
    if ((threadIdx.x & 31) == 0) atomicMax(&sm_, v);
    __syncthreads();
    if (threadIdx.x == 0) atomicMax(&g_pmax, sm_);
}
__global__ void k_scan() {
    __shared__ int part[1024];
    int tid = threadIdx.x, base = tid * 8;
    int loc[8]; int s = 0;
#pragma unroll
    for (int j = 0; j < 8; j++) { loc[j] = g_counts[base + j]; s += loc[j]; }
    part[tid] = s; __syncthreads();
    for (int off = 1; off < 1024; off <<= 1) {
        int v = (tid >= off) ? part[tid - off] : 0;
        __syncthreads(); part[tid] += v; __syncthreads();
    }
    int run = (tid > 0) ? part[tid - 1] : 0;
#pragma unroll
    for (int j = 0; j < 8; j++) { g_offsets[base + j] = run; run += loc[j]; }
}
__global__ void k_scatter(const int* __restrict__ idx, const float* __restrict__ t) {
    int e = blockIdx.x * blockDim.x + threadIdx.x;
    if (e < EMSG) {
        int n = idx[e];
        int p = atomicAdd(&g_cursor[n], 1);
        int slot = g_offsets[n] + p;
        g_ids[slot] = e; g_tk[slot] = t[e];
    }
}
__global__ void k_kbhist() {
    int n = blockIdx.x * blockDim.x + threadIdx.x;
    if (n < NNODE) atomicAdd(&g_kbins[min(g_counts[n], NB - 1)], 1);
}
__global__ void k_kscan() {
    __shared__ int part[NB];
    int tid = threadIdx.x;
    part[tid] = g_kbins[tid]; __syncthreads();
    for (int off = 1; off < NB; off <<= 1) {
        int v = (tid >= off) ? part[tid - off] : 0;
        __syncthreads(); part[tid] += v; __syncthreads();
    }
    g_koff[tid] = (tid > 0) ? part[tid - 1] : 0;
}
__global__ void k_korder() {
    int n = blockIdx.x * blockDim.x + threadIdx.x;
    if (n < NNODE) {
        int kb = min(g_counts[n], NB - 1);
        int p = atomicAdd(&g_kcur[kb], 1);
        g_order[g_koff[kb] + p] = n;
    }
}
__global__ void k_sortgidx() {
    int wg  = (blockIdx.x * blockDim.x + threadIdx.x) >> 5;
    int lane = threadIdx.x & 31;
    if (wg >= NNODE) return;
    int j = wg;
    int n = g_order[NNODE - 1 - j];
    int K = g_counts[n], off = g_offsets[n];
    int Kc = min(K, PCAP);
    if (lane == 0) { g_nodeOf[j] = n; g_Kof[j] = Kc; }
    u64 v0 = ~0ull, v1 = ~0ull;
    if (lane < K)
        v0 = (((u64)__float_as_uint(g_tk[off + lane])) << 32) | (unsigned)g_ids[off + lane];
    if (lane + 32 < K)
        v1 = (((u64)__float_as_uint(g_tk[off + lane + 32])) << 32) | (unsigned)g_ids[off + lane + 32];
#pragma unroll
    for (int k = 2; k <= 64; k <<= 1) {
#pragma unroll
        for (int jj = k >> 1; jj > 0; jj >>= 1) {
            if (jj == 32) {
                u64 lo = v0 < v1 ? v0 : v1;
                u64 hi = v0 < v1 ? v1 : v0;
                v0 = lo; v1 = hi;
            } else {
                u64 p0 = __shfl_xor_sync(0xffffffffu, v0, jj);
                u64 p1 = __shfl_xor_sync(0xffffffffu, v1, jj);
                bool up  = (lane & jj) == 0;
                bool as0 = (lane & k) == 0;
                bool as1 = ((lane + 32) & k) == 0;
                v0 = (as0 == up) ? (v0 < p0 ? v0 : p0) : (v0 < p0 ? p0 : v0);
                v1 = (as1 == up) ? (v1 < p1 ? v1 : p1) : (v1 < p1 ? p1 : v1);
            }
        }
    }
    if (lane < Kc)
        g_gidx[(Kc - lane - 1) * NNODE + j] = (int)(unsigned)(v0 & 0xffffffffull);
    if (lane + 32 < Kc)
        g_gidx[(Kc - lane - 33) * NNODE + j] = (int)(unsigned)(v1 & 0xffffffffull);
}
__global__ void k_transpose(const float* __restrict__ W) {
    int i = blockIdx.x * blockDim.x + threadIdx.x;
    int k = i >> 8, jj = i & 255;
    g_Wp[0][k * DDIM + jj] = W[jj * DDIM + k];
}

// W powers: 64x64 tile, 4x4 per thread
__global__ void __launch_bounds__(256) k_wpow(int half) {
    int r = blockIdx.y + 1, p = half + r;
    if (p > PCAP || p > g_pmax) return;
    const float4* P4 = (const float4*)g_Wp[r - 1];
    const float4* Q4 = (const float4*)g_Wp[half - 1];
    float* C = g_Wp[p - 1];
    int row0 = (blockIdx.x & 3) * 64;
    int col0 = (blockIdx.x >> 2) * 64;
    __shared__ __align__(16) float sPT[16 * 68];
    __shared__ __align__(16) float sQ [16 * 68];
    int tid = threadIdx.x;
    int ty = tid >> 4, tx = tid & 15;
    int pr = tid >> 2, pq = tid & 3;
    int qk = tid >> 4, qc = tid & 15;
    float acc[4][4] = {};
    for (int kc = 0; kc < DDIM; kc += 16) {
        float4 pv = P4[(row0 + pr) * 64 + (kc >> 2) + pq];
        float4 qv = Q4[(kc + qk) * 64 + (col0 >> 2) + qc];
        __syncthreads();
        sPT[(pq * 4 + 0) * 68 + pr] = pv.x;
        sPT[(pq * 4 + 1) * 68 + pr] = pv.y;
        sPT[(pq * 4 + 2) * 68 + pr] = pv.z;
        sPT[(pq * 4 + 3) * 68 + pr] = pv.w;
        *(float4*)&sQ[qk * 68 + qc * 4] = qv;
        __syncthreads();
#pragma unroll
        for (int kk = 0; kk < 16; kk++) {
            float4 a = *(float4*)&sPT[kk * 68 + ty * 4];
            float4 b = *(float4*)&sQ[kk * 68 + tx * 4];
            float ar[4] = {a.x, a.y, a.z, a.w};
            float br[4] = {b.x, b.y, b.z, b.w};
#pragma unroll
            for (int i = 0; i < 4; i++)
#pragma unroll
                for (int j = 0; j < 4; j++)
                    acc[i][j] += ar[i] * br[j];
        }
    }
#pragma unroll
    for (int i = 0; i < 4; i++)
        *(float4*)&C[(row0 + ty * 4 + i) * DDIM + col0 + tx * 4] =
            make_float4(acc[i][0], acc[i][1], acc[i][2], acc[i][3]);
}
__global__ void k_wsplit() {
    int p = blockIdx.y;
    if (p >= g_pmax) return;
    int i = blockIdx.x * 256 + threadIdx.x;
    int pair = i >> 8, jj = i & 255;
    const float* Wt = g_Wp[p];
    float x0 = Wt[(2 * pair) * DDIM + jj];
    float x1 = Wt[(2 * pair + 1) * DDIM + jj];
    unsigned h, l; split2(x0, x1, h, l);
    g_WH[p][pair * DDIM + jj] = h;
    g_WL[p][pair * DDIM + jj] = l;
}
// pre-split messages into bf16 hi/lo, [id][kpair]
__global__ void __launch_bounds__(512) k_msplit(const float* __restrict__ msg) {
    size_t i = (size_t)blockIdx.x * 512 + threadIdx.x;   // float4 index, EMSG*64 total
    float4 v = ((const float4*)msg)[i];
    unsigned h0, l0, h1, l1;
    split2(v.x, v.y, h0, l0);
    split2(v.z, v.w, h1, l1);
    ((u64*)g_MH)[i] = (u64)h0 | ((u64)h1 << 32);
    ((u64*)g_ML)[i] = (u64)l0 | ((u64)l1 << 32);
}
__global__ void k_vj(const float* __restrict__ b) {
    int jj = blockIdx.x + 1;
    if (jj >= g_pmax) return;
    __shared__ float sb[DDIM];
    sb[threadIdx.x] = b[threadIdx.x];
    __syncthreads();
    const float* Wt = g_Wp[jj - 1];
    int i = threadIdx.x;
    float s = 0.f;
#pragma unroll 8
    for (int k = 0; k < DDIM; k++) s += Wt[k * DDIM + i] * sb[k];
    g_v[jj][i] = s;
}
__global__ void k_cbias(const float* __restrict__ b) {
    int i = threadIdx.x;
    float run = 0.f;
    g_cb[0][i] = 0.f;
    for (int K = 1; K <= PCAP; K++) {
        run += (K == 1) ? b[i] : g_v[K - 1][i];
        g_cb[K][i] = run;
    }
}

// ---------------- main kernel: full cp.async 2-stage pipeline ----------------
__global__ void __launch_bounds__(512, 1) k_mma() {
    extern __shared__ __align__(16) char sm[];
    int T = blockIdx.x >> 3, s = blockIdx.x & 7;
    int tid = threadIdx.x;
    int w = tid >> 5, l = tid & 31;
    int g = l >> 2, t = l & 3;
    int wr = w & 3, wc = w >> 2;
    int Kmax = g_Kof[T * TM];
    int nP = (Kmax >= s + 1) ? ((Kmax - (s + 1)) / SST + 1) : 0;
    int C = nP * 8;

    unsigned sAHa = smem_u32(sm + OFF_AH);
    unsigned sALa = smem_u32(sm + OFF_AL);
    unsigned sBHa = smem_u32(sm + OFF_BH);
    unsigned sBLa = smem_u32(sm + OFF_BL);

    float acc[2][8][4];
#pragma unroll
    for (int a = 0; a < 2; a++)
#pragma unroll
        for (int c = 0; c < 8; c++)
#pragma unroll
            for (int q = 0; q < 4; q++) acc[a][c][q] = 0.f;

    int arow = tid >> 2, aq = tid & 3;
    int grow = T * TM + arow;
    int kof = g_Kof[grow];
    int aidPre = -1;

#define CPISSUE(n) do { \
    int b_ = (n) & 1; \
    int p_ = s + 1 + ((n) >> 3) * SST, kc_ = (n) & 7; \
    const unsigned* WH_ = g_WH[p_ - 1] + kc_ * 4096; \
    const unsigned* WL_ = g_WL[p_ - 1] + kc_ * 4096; \
    _Pragma("unroll") \
    for (int u = 0; u < 2; u++) { \
        int f_ = u * 512 + tid; int pr_ = f_ >> 6, j4_ = f_ & 63; \
        unsigned bo_ = (unsigned)(pr_ * 1056 + j4_ * 16); \
        asm volatile("cp.async.cg.shared.global [%0],[%1],16;" \
            :: "r"(sBHa + b_ * 16896u + bo_), "l"((const char*)WH_ + pr_ * 1024 + j4_ * 16)); \
        asm volatile("cp.async.cg.shared.global [%0],[%1],16;" \
            :: "r"(sBLa + b_ * 16896u + bo_), "l"((const char*)WL_ + pr_ * 1024 + j4_ * 16)); \
    } \
    if (kc_ == 0) aidPre = (p_ <= kof) ? g_gidx[(p_ - 1) * NNODE + grow] : -1; \
    { \
        size_t ab_ = (aidPre < 0) ? 0 : ((size_t)aidPre * 512); \
        unsigned sz_ = (aidPre < 0) ? 0u : 16u; \
        unsigned ao_ = (unsigned)(arow * 80 + aq * 16); \
        asm volatile("cp.async.cg.shared.global [%0],[%1],16,%2;" \
            :: "r"(sAHa + b_ * 10240u + ao_), "l"((const char*)g_MH + ab_ + kc_ * 64 + aq * 16), "r"(sz_)); \
        asm volatile("cp.async.cg.shared.global [%0],[%1],16,%2;" \
            :: "r"(sALa + b_ * 10240u + ao_), "l"((const char*)g_ML + ab_ + kc_ * 64 + aq * 16), "r"(sz_)); \
    } \
    asm volatile("cp.async.commit_group;" ::: "memory"); \
} while (0)

    if (C > 0) {
        CPISSUE(0);
        CPISSUE(1);   // C is a multiple of 8, so C >= 8
        for (int c = 0; c < C; c++) {
            if (c + 1 < C) asm volatile("cp.async.wait_group 1;" ::: "memory");
            else           asm volatile("cp.async.wait_group 0;" ::: "memory");
            __syncthreads();

            int buf = c & 1;
            const unsigned* aHb = (const unsigned*)(sm + OFF_AH) + buf * 2560;
            const unsigned* aLb = (const unsigned*)(sm + OFF_AL) + buf * 2560;
            const unsigned* bHb = (const unsigned*)(sm + OFF_BH) + buf * 4224;
            const unsigned* bLb = (const unsigned*)(sm + OFF_BL) + buf * 4224;
#pragma unroll
            for (int kk = 0; kk < 2; kk++) {
                int pl = kk * 8;
                unsigned aH[2][4], aL[2][4];
#pragma unroll
                for (int rt = 0; rt < 2; rt++) {
                    int rb = wr * 32 + rt * 16;
                    aH[rt][0] = aHb[(rb + g) * PAr + pl + t];
                    aH[rt][1] = aHb[(rb + g + 8) * PAr + pl + t];
                    aH[rt][2] = aHb[(rb + g) * PAr + pl + t + 4];
                    aH[rt][3] = aHb[(rb + g + 8) * PAr + pl + t + 4];
                    aL[rt][0] = aLb[(rb + g) * PAr + pl + t];
                    aL[rt][1] = aLb[(rb + g + 8) * PAr + pl + t];
                    aL[rt][2] = aLb[(rb + g) * PAr + pl + t + 4];
                    aL[rt][3] = aLb[(rb + g + 8) * PAr + pl + t + 4];
                }
#pragma unroll
                for (int ct = 0; ct < 8; ct++) {
                    int cb_ = wc * 64 + ct * 8 + g;
                    unsigned bH0 = bHb[(pl + t) * PB + cb_];
                    unsigned bH1 = bHb[(pl + t + 4) * PB + cb_];
                    unsigned bL0 = bLb[(pl + t) * PB + cb_];
                    unsigned bL1 = bLb[(pl + t + 4) * PB + cb_];
#pragma unroll
                    for (int rt = 0; rt < 2; rt++) {
                        MMA_BF16(acc[rt][ct], aH[rt][0], aH[rt][1], aH[rt][2], aH[rt][3], bH0, bH1);
                        MMA_BF16(acc[rt][ct], aH[rt][0], aH[rt][1], aH[rt][2], aH[rt][3], bL0, bL1);
                        MMA_BF16(acc[rt][ct], aL[rt][0], aL[rt][1], aL[rt][2], aL[rt][3], bH0, bH1);
                    }
                }
            }
            __syncthreads();
            if (c + 2 < C) CPISSUE(c + 2);
        }
    }

    float* P = g_part + s * (NNODE * DDIM);
#pragma unroll
    for (int rt = 0; rt < 2; rt++) {
        int row = T * TM + wr * 32 + rt * 16 + g;
#pragma unroll
        for (int ct = 0; ct < 8; ct++) {
            int col = wc * 64 + ct * 8 + t * 2;
            *(float2*)&P[row * DDIM + col]       = make_float2(acc[rt][ct][0], acc[rt][ct][1]);
            *(float2*)&P[(row + 8) * DDIM + col] = make_float2(acc[rt][ct][2], acc[rt][ct][3]);
        }
    }
}

__global__ void k_reduce(float* __restrict__ out) {
    int jj = blockIdx.x, i = threadIdx.x;
    int K = g_Kof[jj];
    float sum = g_cb[K][i];
#pragma unroll
    for (int s = 0; s < SST; s++)
        sum += g_part[s * (NNODE * DDIM) + jj * DDIM + i];
    out[g_nodeOf[jj] * DDIM + i] = sum;
}

// ---------------- launch: proper capture forks for s2 and s3 ----------------
extern "C" void kernel_launch(void* const* d_in, const int* in_sizes, int n_in,
                              void* d_out, int out_size) {
    const float* msg = nullptr; const int* idx = nullptr;
    const float* t = nullptr; const float* W = nullptr; const float* b = nullptr;
    int seenE = 0;
    for (int i = 0; i < n_in; i++) {
        long sz = in_sizes[i];
        if (sz == (long)EMSG * DDIM)      msg = (const float*)d_in[i];
        else if (sz == EMSG) {
            if (seenE == 0) idx = (const int*)d_in[i];
            else            t   = (const float*)d_in[i];
            seenE++;
        }
        else if (sz == DDIM * DDIM)       W = (const float*)d_in[i];
        else if (sz == DDIM)              b = (const float*)d_in[i];
    }

    static cudaStream_t s2, s3;
    static cudaEvent_t eF, e0, e1, e2, e3;
    static int cfg = 0;
    if (!cfg) {
        cudaFuncSetAttribute(k_mma, cudaFuncAttributeMaxDynamicSharedMemorySize, SMEM_SZ);
        cudaStreamCreateWithFlags(&s2, cudaStreamNonBlocking);
        cudaStreamCreateWithFlags(&s3, cudaStreamNonBlocking);
        cudaEventCreateWithFlags(&eF, cudaEventDisableTiming);
        cudaEventCreateWithFlags(&e0, cudaEventDisableTiming);
        cudaEventCreateWithFlags(&e1, cudaEventDisableTiming);
        cudaEventCreateWithFlags(&e2, cudaEventDisableTiming);
        cudaEventCreateWithFlags(&e3, cudaEventDisableTiming);
        cfg = 1;
    }

    // fork s3 from origin FIRST (capture-legal), then presplit msgs there
    cudaEventRecord(eF, 0);
    cudaStreamWaitEvent(s3, eF, 0);
    k_msplit<<<EMSG * 64 / 512, 512, 0, s3>>>(msg);
    cudaEventRecord(e3, s3);

    // main: init + hist
    k_init<<<32,  256>>>();
    k_hist<<<512, 256>>>(idx);
    cudaEventRecord(e0, 0);

    // s2: W chain (pmax-gated), forked after hist
    cudaStreamWaitEvent(s2, e0, 0);
    k_pmax     <<<32,  256, 0, s2>>>();
    k_transpose<<<256, 256, 0, s2>>>(W);
    for (int half = 1; half <= 32; half <<= 1)
        k_wpow<<<dim3(16, half), 256, 0, s2>>>(half);
    k_wsplit<<<dim3(128, PCAP), 256, 0, s2>>>();
    cudaEventRecord(e1, s2);                 // gates k_mma
    k_vj    <<<PCAP - 1, 256, 0, s2>>>(b);
    k_cbias <<<1, 256, 0, s2>>>(b);
    cudaEventRecord(e2, s2);                 // gates k_reduce

    // main: sort chain
    k_scan    <<<1,  1024>>>();
    k_scatter <<<512, 256>>>(idx, t);
    k_kbhist  <<<32,  256>>>();
    k_kscan   <<<1,    NB>>>();
    k_korder  <<<32,  256>>>();
    k_sortgidx<<<1024,256>>>();

    // join
    cudaStreamWaitEvent(0, e1, 0);
    cudaStreamWaitEvent(0, e3, 0);
    k_mma   <<<NTILE * SST, 512, SMEM_SZ>>>();
    cudaStreamWaitEvent(0, e2, 0);
    k_reduce<<<NNODE, 256>>>((float*)d_out);
}

// round 17
// speedup vs baseline: 1.1602x; 1.1602x over previous
#include <cuda_runtime.h>
#include <cuda_fp16.h>

#define EMSG  131072
#define NNODE 8192
#define DDIM  256
#define NB    512
#define PCAP  64
#define TM    128
#define SST   8
#define NTILE (NNODE/TM)
#define PB    264
#define PAr   20

// k_mma dynamic smem (bytes): A(hi only) 2x10240, BH 2x16896, BL 2x16896
#define OFF_AH 0
#define OFF_BH 20480
#define OFF_BL 54272
#define SMEM_SZ 88064

typedef unsigned long long u64;

__device__ int   g_counts [NNODE];
__device__ int   g_offsets[NNODE];
__device__ int   g_cursor [NNODE];
__device__ int   g_ids    [EMSG];
__device__ float g_tk     [EMSG];
__device__ int   g_order  [NNODE];
__device__ int   g_kbins  [NB];
__device__ int   g_koff   [NB];
__device__ int   g_kcur   [NB];
__device__ int   g_pmax;
__device__ int   g_gidx   [PCAP * NNODE];
__device__ int   g_nodeOf [NNODE];
__device__ int   g_Kof    [NNODE];
__device__ __align__(16) float    g_Wp [PCAP][DDIM*DDIM];   // (W^p)^T fp32
__device__ __align__(16) unsigned g_WH [PCAP][128*DDIM];    // W fp16x2 hi (k-pair packed)
__device__ __align__(16) unsigned g_WL [PCAP][128*DDIM];    // W fp16x2 lo (residual)
__device__ __align__(16) unsigned g_MH [EMSG][128];         // msg fp16x2 [id][kpair]
__device__ __align__(16) float    g_v  [PCAP][DDIM];
__device__ __align__(16) float    g_cb [PCAP+1][DDIM];
__device__ __align__(16) float    g_part[SST * NNODE * DDIM];

__device__ __forceinline__ void splitW(float x0, float x1, unsigned& hi, unsigned& lo) {
    __half h0 = __float2half_rn(x0), h1 = __float2half_rn(x1);
    __half l0 = __float2half_rn(x0 - __half2float(h0));
    __half l1 = __float2half_rn(x1 - __half2float(h1));
    __half2 H = __halves2half2(h0, h1);
    __half2 L = __halves2half2(l0, l1);
    hi = *(unsigned*)&H; lo = *(unsigned*)&L;
}

#define MMA_F16(c, A0, A1, A2, A3, B0, B1) \
    asm volatile("mma.sync.aligned.m16n8k16.row.col.f32.f16.f16.f32 " \
        "{%0,%1,%2,%3}, {%4,%5,%6,%7}, {%8,%9}, {%0,%1,%2,%3};" \
        : "+f"(c[0]), "+f"(c[1]), "+f"(c[2]), "+f"(c[3]) \
        : "r"(A0), "r"(A1), "r"(A2), "r"(A3), "r"(B0), "r"(B1))

static __device__ __forceinline__ unsigned smem_u32(const void* p) {
    unsigned a;
    asm("{ .reg .u64 t; cvta.to.shared.u64 t, %1; cvt.u32.u64 %0, t; }" : "=r"(a) : "l"(p));
    return a;
}

// ---------------- setup ----------------
__global__ void k_init() {
    int i = blockIdx.x * blockDim.x + threadIdx.x;
    if (i < NNODE) { g_counts[i] = 0; g_cursor[i] = 0; }
    if (i < NB)    { g_kbins[i]  = 0; g_kcur[i]   = 0; }
    if (i == 0)    g_pmax = 0;
}
__global__ void k_hist(const int* __restrict__ idx) {
    int e = blockIdx.x * blockDim.x + threadIdx.x;
    if (e < EMSG) atomicAdd(&g_counts[idx[e]], 1);
}
__global__ void k_pmax() {
    __shared__ int sm_;
    if (threadIdx.x == 0) sm_ = 0;
    __syncthreads();
    int n = blockIdx.x * blockDim.x + threadIdx.x;
    int v = (n < NNODE) ? min(g_counts[n], PCAP) : 0;
#pragma unroll
    for (int o = 16; o > 0; o >>= 1) v = max(v, __shfl_down_sync(~0u, v, o));
    if ((threadIdx.x & 31) == 0) atomicMax(&sm_, v);
    __syncthreads();
    if (threadIdx.x == 0) atomicMax(&g_pmax, sm_);
}
__global__ void k_scan() {
    __shared__ int part[1024];
    int tid = threadIdx.x, base = tid * 8;
    int loc[8]; int s = 0;
#pragma unroll
    for (int j = 0; j < 8; j++) { loc[j] = g_counts[base + j]; s += loc[j]; }
    part[tid] = s; __syncthreads();
    for (int off = 1; off < 1024; off <<= 1) {
        int v = (tid >= off) ? part[tid - off] : 0;
        __syncthreads(); part[tid] += v; __syncthreads();
    }
    int run = (tid > 0) ? part[tid - 1] : 0;
#pragma unroll
    for (int j = 0; j < 8; j++) { g_offsets[base + j] = run; run += loc[j]; }
}
__global__ void k_scatter(const int* __restrict__ idx, const float* __restrict__ t) {
    int e = blockIdx.x * blockDim.x + threadIdx.x;
    if (e < EMSG) {
        int n = idx[e];
        int p = atomicAdd(&g_cursor[n], 1);
        int slot = g_offsets[n] + p;
        g_ids[slot] = e; g_tk[slot] = t[e];
    }
}
__global__ void k_kbhist() {
    int n = blockIdx.x * blockDim.x + threadIdx.x;
    if (n < NNODE) atomicAdd(&g_kbins[min(g_counts[n], NB - 1)], 1);
}
__global__ void k_kscan() {
    __shared__ int part[NB];
    int tid = threadIdx.x;
    part[tid] = g_kbins[tid]; __syncthreads();
    for (int off = 1; off < NB; off <<= 1) {
        int v = (tid >= off) ? part[tid - off] : 0;
        __syncthreads(); part[tid] += v; __syncthreads();
    }
    g_koff[tid] = (tid > 0) ? part[tid - 1] : 0;
}
__global__ void k_korder() {
    int n = blockIdx.x * blockDim.x + threadIdx.x;
    if (n < NNODE) {
        int kb = min(g_counts[n], NB - 1);
        int p = atomicAdd(&g_kcur[kb], 1);
        g_order[g_koff[kb] + p] = n;
    }
}
__global__ void k_sortgidx() {
    int wg  = (blockIdx.x * blockDim.x + threadIdx.x) >> 5;
    int lane = threadIdx.x & 31;
    if (wg >= NNODE) return;
    int j = wg;
    int n = g_order[NNODE - 1 - j];
    int K = g_counts[n], off = g_offsets[n];
    int Kc = min(K, PCAP);
    if (lane == 0) { g_nodeOf[j] = n; g_Kof[j] = Kc; }
    u64 v0 = ~0ull, v1 = ~0ull;
    if (lane < K)
        v0 = (((u64)__float_as_uint(g_tk[off + lane])) << 32) | (unsigned)g_ids[off + lane];
    if (lane + 32 < K)
        v1 = (((u64)__float_as_uint(g_tk[off + lane + 32])) << 32) | (unsigned)g_ids[off + lane + 32];
#pragma unroll
    for (int k = 2; k <= 64; k <<= 1) {
#pragma unroll
        for (int jj = k >> 1; jj > 0; jj >>= 1) {
            if (jj == 32) {
                u64 lo = v0 < v1 ? v0 : v1;
                u64 hi = v0 < v1 ? v1 : v0;
                v0 = lo; v1 = hi;
            } else {
                u64 p0 = __shfl_xor_sync(0xffffffffu, v0, jj);
                u64 p1 = __shfl_xor_sync(0xffffffffu, v1, jj);
                bool up  = (lane & jj) == 0;
                bool as0 = (lane & k) == 0;
                bool as1 = ((lane + 32) & k) == 0;
                v0 = (as0 == up) ? (v0 < p0 ? v0 : p0) : (v0 < p0 ? p0 : v0);
                v1 = (as1 == up) ? (v1 < p1 ? v1 : p1) : (v1 < p1 ? p1 : v1);
            }
        }
    }
    if (lane < Kc)
        g_gidx[(Kc - lane - 1) * NNODE + j] = (int)(unsigned)(v0 & 0xffffffffull);
    if (lane + 32 < Kc)
        g_gidx[(Kc - lane - 33) * NNODE + j] = (int)(unsigned)(v1 & 0xffffffffull);
}
__global__ void k_transpose(const float* __restrict__ W) {
    int i = blockIdx.x * blockDim.x + threadIdx.x;
    int k = i >> 8, jj = i & 255;
    g_Wp[0][k * DDIM + jj] = W[jj * DDIM + k];
}
// W powers: 64x64 tile, 4x4 per thread
__global__ void __launch_bounds__(256) k_wpow(int half) {
    int r = blockIdx.y + 1, p = half + r;
    if (p > PCAP || p > g_pmax) return;
    const float4* P4 = (const float4*)g_Wp[r - 1];
    const float4* Q4 = (const float4*)g_Wp[half - 1];
    float* C = g_Wp[p - 1];
    int row0 = (blockIdx.x & 3) * 64;
    int col0 = (blockIdx.x >> 2) * 64;
    __shared__ __align__(16) float sPT[16 * 68];
    __shared__ __align__(16) float sQ [16 * 68];
    int tid = threadIdx.x;
    int ty = tid >> 4, tx = tid & 15;
    int pr = tid >> 2, pq = tid & 3;
    int qk = tid >> 4, qc = tid & 15;
    float acc[4][4] = {};
    for (int kc = 0; kc < DDIM; kc += 16) {
        float4 pv = P4[(row0 + pr) * 64 + (kc >> 2) + pq];
        float4 qv = Q4[(kc + qk) * 64 + (col0 >> 2) + qc];
        __syncthreads();
        sPT[(pq * 4 + 0) * 68 + pr] = pv.x;
        sPT[(pq * 4 + 1) * 68 + pr] = pv.y;
        sPT[(pq * 4 + 2) * 68 + pr] = pv.z;
        sPT[(pq * 4 + 3) * 68 + pr] = pv.w;
        *(float4*)&sQ[qk * 68 + qc * 4] = qv;
        __syncthreads();
#pragma unroll
        for (int kk = 0; kk < 16; kk++) {
            float4 a = *(float4*)&sPT[kk * 68 + ty * 4];
            float4 b = *(float4*)&sQ[kk * 68 + tx * 4];
            float ar[4] = {a.x, a.y, a.z, a.w};
            float br[4] = {b.x, b.y, b.z, b.w};
#pragma unroll
            for (int i = 0; i < 4; i++)
#pragma unroll
                for (int j = 0; j < 4; j++)
                    acc[i][j] += ar[i] * br[j];
        }
    }
#pragma unroll
    for (int i = 0; i < 4; i++)
        *(float4*)&C[(row0 + ty * 4 + i) * DDIM + col0 + tx * 4] =
            make_float4(acc[i][0], acc[i][1], acc[i][2], acc[i][3]);
}
// fp16 hi/lo k-pair packed: g_WH[p][pair*256+j] = half2{Wt[2k][j], Wt[2k+1][j]}
__global__ void k_wsplit() {
    int p = blockIdx.y;
    if (p >= g_pmax) return;
    int i = blockIdx.x * 256 + threadIdx.x;
    int pair = i >> 8, jj = i & 255;
    const float* Wt = g_Wp[p];
    float x0 = Wt[(2 * pair) * DDIM + jj];
    float x1 = Wt[(2 * pair + 1) * DDIM + jj];
    unsigned h, l; splitW(x0, x1, h, l);
    g_WH[p][pair * DDIM + jj] = h;
    g_WL[p][pair * DDIM + jj] = l;
}
// pre-convert messages to fp16, [id][kpair]
__global__ void __launch_bounds__(512) k_msplit(const float* __restrict__ msg) {
    size_t i = (size_t)blockIdx.x * 512 + threadIdx.x;   // float4 index, EMSG*64 total
    float4 v = ((const float4*)msg)[i];
    __half2 p0 = __floats2half2_rn(v.x, v.y);
    __half2 p1 = __floats2half2_rn(v.z, v.w);
    u64 out = (u64)(*(unsigned*)&p0) | ((u64)(*(unsigned*)&p1) << 32);
    ((u64*)g_MH)[i] = out;
}
__global__ void k_vj(const float* __restrict__ b) {
    int jj = blockIdx.x + 1;
    if (jj >= g_pmax) return;
    __shared__ float sb[DDIM];
    sb[threadIdx.x] = b[threadIdx.x];
    __syncthreads();
    const float* Wt = g_Wp[jj - 1];
    int i = threadIdx.x;
    float s = 0.f;
#pragma unroll 8
    for (int k = 0; k < DDIM; k++) s += Wt[k * DDIM + i] * sb[k];
    g_v[jj][i] = s;
}
__global__ void k_cbias(const float* __restrict__ b) {
    int i = threadIdx.x;
    float run = 0.f;
    g_cb[0][i] = 0.f;
    for (int K = 1; K <= PCAP; K++) {
        run += (K == 1) ? b[i] : g_v[K - 1][i];
        g_cb[K][i] = run;
    }
}

// ---------------- main kernel: fp16 2-term, cp.async 2-stage ----------------
__global__ void __launch_bounds__(512, 1) k_mma() {
    extern __shared__ __align__(16) char sm[];
    int T = blockIdx.x >> 3, s = blockIdx.x & 7;
    int tid = threadIdx.x;
    int w = tid >> 5, l = tid & 31;
    int g = l >> 2, t = l & 3;
    int wr = w & 3, wc = w >> 2;
    int Kmax = g_Kof[T * TM];
    int nP = (Kmax >= s + 1) ? ((Kmax - (s + 1)) / SST + 1) : 0;
    int C = nP * 8;

    unsigned sAHa = smem_u32(sm + OFF_AH);
    unsigned sBHa = smem_u32(sm + OFF_BH);
    unsigned sBLa = smem_u32(sm + OFF_BL);

    float acc[2][8][4];
#pragma unroll
    for (int a = 0; a < 2; a++)
#pragma unroll
        for (int c = 0; c < 8; c++)
#pragma unroll
            for (int q = 0; q < 4; q++) acc[a][c][q] = 0.f;

    int arow = tid >> 2, aq = tid & 3;
    int grow = T * TM + arow;
    int kof = g_Kof[grow];
    int aidPre = -1;

#define CPISSUE(n) do { \
    int b_ = (n) & 1; \
    int p_ = s + 1 + ((n) >> 3) * SST, kc_ = (n) & 7; \
    const unsigned* WH_ = g_WH[p_ - 1] + kc_ * 4096; \
    const unsigned* WL_ = g_WL[p_ - 1] + kc_ * 4096; \
    _Pragma("unroll") \
    for (int u = 0; u < 2; u++) { \
        int f_ = u * 512 + tid; int pr_ = f_ >> 6, j4_ = f_ & 63; \
        unsigned bo_ = (unsigned)(pr_ * 1056 + j4_ * 16); \
        asm volatile("cp.async.cg.shared.global [%0],[%1],16;" \
            :: "r"(sBHa + b_ * 16896u + bo_), "l"((const char*)WH_ + pr_ * 1024 + j4_ * 16)); \
        asm volatile("cp.async.cg.shared.global [%0],[%1],16;" \
            :: "r"(sBLa + b_ * 16896u + bo_), "l"((const char*)WL_ + pr_ * 1024 + j4_ * 16)); \
    } \
    if (kc_ == 0) aidPre = (p_ <= kof) ? g_gidx[(p_ - 1) * NNODE + grow] : -1; \
    { \
        size_t ab_ = (aidPre < 0) ? 0 : ((size_t)aidPre * 512); \
        unsigned sz_ = (aidPre < 0) ? 0u : 16u; \
        unsigned ao_ = (unsigned)(arow * 80 + aq * 16); \
        asm volatile("cp.async.cg.shared.global [%0],[%1],16,%2;" \
            :: "r"(sAHa + b_ * 10240u + ao_), "l"((const char*)g_MH + ab_ + kc_ * 64 + aq * 16), "r"(sz_)); \
    } \
    asm volatile("cp.async.commit_group;" ::: "memory"); \
} while (0)

    if (C > 0) {
        CPISSUE(0);
        CPISSUE(1);   // C is a multiple of 8, so C >= 8
        for (int c = 0; c < C; c++) {
            if (c + 1 < C) asm volatile("cp.async.wait_group 1;" ::: "memory");
            else           asm volatile("cp.async.wait_group 0;" ::: "memory");
            __syncthreads();

            int buf = c & 1;
            const unsigned* aHb = (const unsigned*)(sm + OFF_AH) + buf * 2560;
            const unsigned* bHb = (const unsigned*)(sm + OFF_BH) + buf * 4224;
            const unsigned* bLb = (const unsigned*)(sm + OFF_BL) + buf * 4224;
#pragma unroll
            for (int kk = 0; kk < 2; kk++) {
                int pl = kk * 8;
                unsigned aH[2][4];
#pragma unroll
                for (int rt = 0; rt < 2; rt++) {
                    int rb = wr * 32 + rt * 16;
                    aH[rt][0] = aHb[(rb + g) * PAr + pl + t];
                    aH[rt][1] = aHb[(rb + g + 8) * PAr + pl + t];
                    aH[rt][2] = aHb[(rb + g) * PAr + pl + t + 4];
                    aH[rt][3] = aHb[(rb + g + 8) * PAr + pl + t + 4];
                }
#pragma unroll
                for (int ct = 0; ct < 8; ct++) {
                    int cb_ = wc * 64 + ct * 8 + g;
                    unsigned bH0 = bHb[(pl + t) * PB + cb_];
                    unsigned bH1 = bHb[(pl + t + 4) * PB + cb_];
                    unsigned bL0 = bLb[(pl + t) * PB + cb_];
                    unsigned bL1 = bLb[(pl + t + 4) * PB + cb_];
#pragma unroll
                    for (int rt = 0; rt < 2; rt++) {
                        MMA_F16(acc[rt][ct], aH[rt][0], aH[rt][1], aH[rt][2], aH[rt][3], bH0, bH1);
                        MMA_F16(acc[rt][ct], aH[rt][0], aH[rt][1], aH[rt][2], aH[rt][3], bL0, bL1);
                    }
                }
            }
            __syncthreads();
            if (c + 2 < C) CPISSUE(c + 2);
        }
    }

    float* P = g_part + s * (NNODE * DDIM);
#pragma unroll
    for (int rt = 0; rt < 2; rt++) {
        int row = T * TM + wr * 32 + rt * 16 + g;
#pragma unroll
        for (int ct = 0; ct < 8; ct++) {
            int col = wc * 64 + ct * 8 + t * 2;
            *(float2*)&P[row * DDIM + col]       = make_float2(acc[rt][ct][0], acc[rt][ct][1]);
            *(float2*)&P[(row + 8) * DDIM + col] = make_float2(acc[rt][ct][2], acc[rt][ct][3]);
        }
    }
}

__global__ void k_reduce(float* __restrict__ out) {
    int jj = blockIdx.x, i = threadIdx.x;
    int K = g_Kof[jj];
    float sum = g_cb[K][i];
#pragma unroll
    for (int s = 0; s < SST; s++)
        sum += g_part[s * (NNODE * DDIM) + jj * DDIM + i];
    out[g_nodeOf[jj] * DDIM + i] = sum;
}

// ---------------- launch: 3 streams, capture-legal forks ----------------
extern "C" void kernel_launch(void* const* d_in, const int* in_sizes, int n_in,
                              void* d_out, int out_size) {
    const float* msg = nullptr; const int* idx = nullptr;
    const float* t = nullptr; const float* W = nullptr; const float* b = nullptr;
    int seenE = 0;
    for (int i = 0; i < n_in; i++) {
        long sz = in_sizes[i];
        if (sz == (long)EMSG * DDIM)      msg = (const float*)d_in[i];
        else if (sz == EMSG) {
            if (seenE == 0) idx = (const int*)d_in[i];
            else            t   = (const float*)d_in[i];
            seenE++;
        }
        else if (sz == DDIM * DDIM)       W = (const float*)d_in[i];
        else if (sz == DDIM)              b = (const float*)d_in[i];
    }

    static cudaStream_t s2, s3;
    static cudaEvent_t eF, e0, e1, e2, e3;
    static int cfg = 0;
    if (!cfg) {
        cudaFuncSetAttribute(k_mma, cudaFuncAttributeMaxDynamicSharedMemorySize, SMEM_SZ);
        cudaStreamCreateWithFlags(&s2, cudaStreamNonBlocking);
        cudaStreamCreateWithFlags(&s3, cudaStreamNonBlocking);
        cudaEventCreateWithFlags(&eF, cudaEventDisableTiming);
        cudaEventCreateWithFlags(&e0, cudaEventDisableTiming);
        cudaEventCreateWithFlags(&e1, cudaEventDisableTiming);
        cudaEventCreateWithFlags(&e2, cudaEventDisableTiming);
        cudaEventCreateWithFlags(&e3, cudaEventDisableTiming);
        cfg = 1;
    }

    // fork s3 from origin (capture-legal), then convert msgs there
    cudaEventRecord(eF, 0);
    cudaStreamWaitEvent(s3, eF, 0);
    k_msplit<<<EMSG * 64 / 512, 512, 0, s3>>>(msg);
    cudaEventRecord(e3, s3);

    // main: init + hist
    k_init<<<32,  256>>>();
    k_hist<<<512, 256>>>(idx);
    cudaEventRecord(e0, 0);

    // s2: W chain (pmax-gated)
    cudaStreamWaitEvent(s2, e0, 0);
    k_pmax     <<<32,  256, 0, s2>>>();
    k_transpose<<<256, 256, 0, s2>>>(W);
    for (int half = 1; half <= 32; half <<= 1)
        k_wpow<<<dim3(16, half), 256, 0, s2>>>(half);
    k_wsplit<<<dim3(128, PCAP), 256, 0, s2>>>();
    cudaEventRecord(e1, s2);                 // gates k_mma
    k_vj    <<<PCAP - 1, 256, 0, s2>>>(b);
    k_cbias <<<1, 256, 0, s2>>>(b);
    cudaEventRecord(e2, s2);                 // gates k_reduce

    // main: sort chain
    k_scan    <<<1,  1024>>>();
    k_scatter <<<512, 256>>>(idx, t);
    k_kbhist  <<<32,  256>>>();
    k_kscan   <<<1,    NB>>>();
    k_korder  <<<32,  256>>>();
    k_sortgidx<<<1024,256>>>();

    // join
    cudaStreamWaitEvent(0, e1, 0);
    cudaStreamWaitEvent(0, e3, 0);
    k_mma   <<<NTILE * SST, 512, SMEM_SZ>>>();
    cudaStreamWaitEvent(0, e2, 0);
    k_reduce<<<NNODE, 256>>>((float*)d_out);
}